// round 7
// baseline (speedup 1.0000x reference)
#include <cuda_runtime.h>
#include <cstdint>

#define DB 64
#define DS 2048
#define DI 64
#define DH 128

typedef unsigned long long u64;

// ---------------- scratch (__device__ globals) -------------------------------
__device__ float g_wx0 [DB * DS * DH];   // x @ w0      (proj CTAs)
__device__ float g_out0[DB * DS * DH];   // layer-0 out (producer scan)
__device__ float g_wx1 [DB * DS * DH];   // out0 @ w1   (proj CTAs)
__device__ int   g_prog[DB * 32];        // [b*32]=p0  [+8]=pwx0  [+16]=pwx1

// ---------------- packed f32x2 helpers ---------------------------------------
__device__ __forceinline__ u64 ffma2(u64 a, u64 b, u64 c) {
    u64 d; asm("fma.rn.f32x2 %0, %1, %2, %3;" : "=l"(d) : "l"(a), "l"(b), "l"(c)); return d;
}
__device__ __forceinline__ u64 fadd2(u64 a, u64 b) {
    u64 d; asm("add.rn.f32x2 %0, %1, %2;" : "=l"(d) : "l"(a), "l"(b)); return d;
}
__device__ __forceinline__ u64 dup2(float x) {
    u64 d; asm("mov.b64 %0, {%1, %2};" : "=l"(d) : "f"(x), "f"(x)); return d;
}
__device__ __forceinline__ u64 pk2(float lo, float hi) {
    u64 d; asm("mov.b64 %0, {%1, %2};" : "=l"(d) : "f"(lo), "f"(hi)); return d;
}
__device__ __forceinline__ float2 unp2(u64 v) {
    float lo, hi; asm("mov.b64 {%0, %1}, %2;" : "=f"(lo), "=f"(hi) : "l"(v));
    return make_float2(lo, hi);
}

// ---------------- fast gates (verified rel_err 1.3e-7 in R6) ------------------
__device__ __forceinline__ float sigm_fast(float x) {
    float t, r;
    asm("ex2.approx.f32 %0, %1;" : "=f"(t) : "f"(-1.4426950408889634f * x));
    asm("rcp.approx.f32 %0, %1;" : "=f"(r) : "f"(1.0f + t));
    return r;
}
__device__ __forceinline__ float tanh_fast(float x) {
    float t, r;
    asm("ex2.approx.f32 %0, %1;" : "=f"(t) : "f"(-2.8853900817779268f * x));
    asm("rcp.approx.f32 %0, %1;" : "=f"(r) : "f"(1.0f + t));
    return __fmaf_rn(2.0f, r, -1.0f);
}

// ---------------- flags --------------------------------------------------------
__device__ __forceinline__ int ld_acq(const int* p) {
    int v; asm volatile("ld.acquire.gpu.b32 %0, [%1];" : "=r"(v) : "l"(p)); return v;
}
__device__ __forceinline__ void st_rel(int* p, int v) {
    asm volatile("st.release.gpu.b32 [%0], %1;" :: "l"(p), "r"(v));
}
__device__ __forceinline__ void spin_ge(const int* p, int target) {
    while (ld_acq(p) < target) __nanosleep(32);
}

__global__ void reset_kernel() {
    int i = blockIdx.x * blockDim.x + threadIdx.x;
    if (i < DB * 32) g_prog[i] = 0;
}

// ============================================================================
// Scan role: 256 threads; thread = (col j = tid>>1, khalf = tid&1).
// pre[j] = wx[s][j] + sum_k h[k]*u[k][j]; halves combined via shfl.xor(1).
// One __syncthreads per step; depth-2 h ping-pong; wx depth-2 reg prefetch.
// ============================================================================
__device__ void scan_role(
    float* __restrict__ hbuf,                      // smem, 2*DH floats
    const float* __restrict__ umat, const float* __restrict__ wx,
    const float* __restrict__ bg, const float* __restrict__ bu,
    const float* __restrict__ zeta, const float* __restrict__ nu,
    const float* __restrict__ lambd, const float* __restrict__ gamma,
    float* __restrict__ outp, float* __restrict__ hT,
    const int* pwait, int* ppost, int tid)
{
    const int j  = tid >> 1;
    const int kh = tid & 1;

    // weights: k-pair packed {u[k][j], u[k+1][j]}, k in [kh*64, kh*64+64)
    u64 uk[32];
    #pragma unroll
    for (int i = 0; i < 32; i++) {
        int k = kh * 64 + 2 * i;
        uk[i] = pk2(umat[(size_t)k * DH + j], umat[(size_t)(k + 1) * DH + j]);
    }
    const float bgj  = bg[j], buj = bu[j];
    const float sz   = sigm_fast(zeta[0]);
    const float sn   = sigm_fast(nu[0]);
    const float gc   = fminf(fmaxf(gamma[0], 0.f), 1.f);
    const float cadd = (1.f - gc) * lambd[0];

    hbuf[tid] = 0.f;                               // zero both buffers
    if (tid == 0) spin_ge(pwait, 18 < DS ? 18 : DS);
    __syncthreads();

    float hold = 0.f, wxA = 0.f, wxB = 0.f;
    if (kh == 0) { wxA = wx[j]; wxB = wx[DH + j]; }

    #pragma unroll 1
    for (int s = 0; s < DS; s++) {
        if ((s & 15) == 0 && s) {
            if (tid == 0) {
                int t = s + 18; if (t > DS) t = DS;
                spin_ge(pwait, t);
            }
            __syncthreads();
        }
        const ulonglong2* hp =
            reinterpret_cast<const ulonglong2*>(hbuf + (s & 1) * DH + kh * 64);
        u64 a0 = 0, a1 = 0, a2 = 0, a3 = 0;
        #pragma unroll
        for (int t = 0; t < 8; t++) {
            ulonglong2 q0 = hp[2*t], q1 = hp[2*t + 1];
            a0 = ffma2(q0.x, uk[4*t + 0], a0);
            a1 = ffma2(q0.y, uk[4*t + 1], a1);
            a2 = ffma2(q1.x, uk[4*t + 2], a2);
            a3 = ffma2(q1.y, uk[4*t + 3], a3);
        }
        u64 acc = fadd2(fadd2(a0, a1), fadd2(a2, a3));
        acc = fadd2(acc, __shfl_xor_sync(0xFFFFFFFFu, acc, 1));
        float2 ap = unp2(acc);
        float pre = ap.x + ap.y;
        if (kh == 0) {
            pre += wxA;
            float zg = sigm_fast(pre + bgj);
            float th = tanh_fast(pre + buj);
            float hn = zg * hold + (sz * (1.f - zg) + sn) * th;
            float hc = __fmaf_rn(gc, hn, cadd);
            hold = hc;
            hbuf[((s & 1) ^ 1) * DH + j] = hc;
            outp[(size_t)s * DH + j] = hc;
            wxA = wxB;
            wxB = (s + 2 < DS) ? wx[(size_t)(s + 2) * DH + j] : 0.f;
        }
        __syncthreads();
        if (ppost && (s & 7) == 7 && tid == 0) {
            __threadfence();
            st_rel(ppost, s + 1);
        }
    }
    if (kh == 0) hT[j] = hold;
}

// ============================================================================
// Projection tile: dst[t0..t0+15, 0:128] = SRC[t0..t0+15, 0:K] @ W
// (verified structure from R4). Warp = 2 tile rows; lane owns col-pairs l, l+32.
// ============================================================================
template<int K>
__device__ __forceinline__ void proj_tile(
    const float* __restrict__ src, int t0,
    const float4* __restrict__ wpack, float* __restrict__ stage,
    float* __restrict__ dst, int tid)
{
    for (int e = tid; e < 16 * K / 4; e += 256)
        reinterpret_cast<float4*>(stage)[e] =
            reinterpret_cast<const float4*>(src + (size_t)t0 * K)[e];
    __syncthreads();

    const int r2 = tid >> 5;
    const int l  = tid & 31;
    #pragma unroll 1
    for (int rr = 0; rr < 2; rr++) {
        const int row = 2 * r2 + rr;
        const float* srow = stage + row * K;
        u64 aA = 0, bA = 0, aB = 0, bB = 0;
        #pragma unroll 8
        for (int k2 = 0; k2 < K / 2; k2++) {
            float2 s2 = *reinterpret_cast<const float2*>(srow + 2 * k2);
            u64 d0 = dup2(s2.x), d1 = dup2(s2.y);
            float4 wa = wpack[k2 * 64 + l];
            float4 wb = wpack[k2 * 64 + l + 32];
            aA = ffma2(d0, pk2(wa.x, wa.y), aA);
            bA = ffma2(d1, pk2(wa.z, wa.w), bA);
            aB = ffma2(d0, pk2(wb.x, wb.y), aB);
            bB = ffma2(d1, pk2(wb.z, wb.w), bB);
        }
        *reinterpret_cast<u64*>(dst + (size_t)(t0 + row) * DH + 2 * l)      = fadd2(aA, bA);
        *reinterpret_cast<u64*>(dst + (size_t)(t0 + row) * DH + 64 + 2 * l) = fadd2(aB, bB);
    }
    __syncthreads();
}

// ============================================================================
// Proj role: wx0 (8-tile head start, then low priority) + wx1 (chases p0).
// ============================================================================
__device__ void proj_role(
    const float* __restrict__ xb, const float* __restrict__ out0b,
    const float* __restrict__ w0, const float* __restrict__ w1,
    float* __restrict__ wx0b, float* __restrict__ wx1b,
    const int* p0, int* pwx0, int* pwx1,
    float4* wp0, float4* wp1, float* stage, int tid)
{
    __shared__ int sp0;

    // pack weights into smem
    for (int e = tid; e < 32 * 64; e += 256) {
        int k2 = e >> 6, c = e & 63;
        const float* r0 = w0 + (size_t)(2 * k2) * DH + 2 * c;
        wp0[e] = make_float4(r0[0], r0[1], r0[DH], r0[DH + 1]);
    }
    for (int e = tid; e < 64 * 64; e += 256) {
        int k2 = e >> 6, c = e & 63;
        const float* r0 = w1 + (size_t)(2 * k2) * DH + 2 * c;
        wp1[e] = make_float4(r0[0], r0[1], r0[DH], r0[DH + 1]);
    }
    __syncthreads();

    const int NT = DS / 16;      // 128 tiles per stream
    int n0 = 0, n1 = 0;

    // head start: 8 wx0 tiles (producer needs wx0[0..17] to start)
    #pragma unroll 1
    for (; n0 < 8; n0++) {
        proj_tile<DI>(xb, n0 * 16, wp0, stage, wx0b, tid);
        if (tid == 0) { __threadfence(); st_rel(pwx0, n0 * 16 + 16); }
    }

    #pragma unroll 1
    while (n0 < NT || n1 < NT) {
        int ready = 0;
        if (n1 < NT) {
            if (tid == 0) sp0 = ld_acq(p0);
            __syncthreads();
            ready = (sp0 >= n1 * 16 + 16);
            __syncthreads();
        }
        if (ready) {
            proj_tile<DH>(out0b, n1 * 16, wp1, stage, wx1b, tid);
            if (tid == 0) { __threadfence(); st_rel(pwx1, n1 * 16 + 16); }
            n1++;
        } else if (n0 < NT) {
            proj_tile<DI>(xb, n0 * 16, wp0, stage, wx0b, tid);
            if (tid == 0) { __threadfence(); st_rel(pwx0, n0 * 16 + 16); }
            n0++;
        } else {
            if (tid == 0) spin_ge(p0, n1 * 16 + 16);
            __syncthreads();
        }
    }
}

// ============================================================================
__global__ void __launch_bounds__(256, 2) mega_kernel(
    const float* __restrict__ x,
    const float* __restrict__ w0, const float* __restrict__ u0,
    const float* __restrict__ bg0, const float* __restrict__ bu0,
    const float* __restrict__ zeta0, const float* __restrict__ nu0,
    const float* __restrict__ lambd0, const float* __restrict__ gamma0,
    const float* __restrict__ w1, const float* __restrict__ u1,
    const float* __restrict__ bg1, const float* __restrict__ bu1,
    const float* __restrict__ zeta1, const float* __restrict__ nu1,
    const float* __restrict__ lambd1, const float* __restrict__ gamma1,
    float* __restrict__ out1, float* __restrict__ hT0, float* __restrict__ hT1)
{
    extern __shared__ __align__(16) unsigned char smraw[];
    const int tid  = threadIdx.x;
    const int role = blockIdx.x >> 6;   // 0=producer scan, 1=consumer scan, 2=proj
    const int b    = blockIdx.x & 63;

    float*       out0b = g_out0 + (size_t)b * DS * DH;
    float*       wx0b  = g_wx0  + (size_t)b * DS * DH;
    float*       wx1b  = g_wx1  + (size_t)b * DS * DH;
    int*         p0    = g_prog + b * 32;
    int*         pwx0  = g_prog + b * 32 + 8;
    int*         pwx1  = g_prog + b * 32 + 16;

    if (role == 0) {
        float* hbuf = reinterpret_cast<float*>(smraw);
        scan_role(hbuf, u0, wx0b, bg0, bu0, zeta0, nu0, lambd0, gamma0,
                  out0b, hT0 + (size_t)b * DH, pwx0, p0, tid);
    } else if (role == 1) {
        float* hbuf = reinterpret_cast<float*>(smraw);
        scan_role(hbuf, u1, wx1b, bg1, bu1, zeta1, nu1, lambd1, gamma1,
                  out1 + (size_t)b * DS * DH, hT1 + (size_t)b * DH,
                  pwx1, nullptr, tid);
    } else {
        float4* wp0 = reinterpret_cast<float4*>(smraw);                  // 32KB
        float4* wp1 = reinterpret_cast<float4*>(smraw + 32768);         // 64KB
        float*  stg = reinterpret_cast<float*>(smraw + 32768 + 65536);  // 8KB
        proj_role(x + (size_t)b * DS * DI, out0b, w0, w1,
                  wx0b, wx1b, p0, pwx0, pwx1, wp0, wp1, stg, tid);
    }
}

// ============================================================================
extern "C" void kernel_launch(void* const* d_in, const int* in_sizes, int n_in,
                              void* d_out, int out_size)
{
    const float* x      = (const float*)d_in[0];
    const float* w0     = (const float*)d_in[1];
    const float* u0     = (const float*)d_in[2];
    const float* bg0    = (const float*)d_in[3];
    const float* bu0    = (const float*)d_in[4];
    const float* zeta0  = (const float*)d_in[5];
    const float* nu0    = (const float*)d_in[6];
    const float* lambd0 = (const float*)d_in[7];
    const float* gamma0 = (const float*)d_in[8];
    const float* w1     = (const float*)d_in[9];
    const float* u1     = (const float*)d_in[10];
    const float* bg1    = (const float*)d_in[11];
    const float* bu1    = (const float*)d_in[12];
    const float* zeta1  = (const float*)d_in[13];
    const float* nu1    = (const float*)d_in[14];
    const float* lambd1 = (const float*)d_in[15];
    const float* gamma1 = (const float*)d_in[16];
    (void)in_sizes; (void)n_in; (void)out_size;

    float* out = (float*)d_out;                    // out1: [B, S, H]
    float* hT0 = out + (size_t)DB * DS * DH;       // h_n[0]
    float* hT1 = hT0 + (size_t)DB * DH;            // h_n[1]

    const int smem_bytes = 32768 + 65536 + 8192;   // 106496 (proj footprint)
    static int smem_set = 0;
    if (!smem_set) {
        cudaFuncSetAttribute(mega_kernel,
                             cudaFuncAttributeMaxDynamicSharedMemorySize, smem_bytes);
        smem_set = 1;
    }

    reset_kernel<<<2, 1024>>>();
    mega_kernel<<<3 * DB, 256, smem_bytes>>>(
        x, w0, u0, bg0, bu0, zeta0, nu0, lambd0, gamma0,
        w1, u1, bg1, bu1, zeta1, nu1, lambd1, gamma1,
        out, hT0, hT1);
}

// round 8
// speedup vs baseline: 1.3511x; 1.3511x over previous
#include <cuda_runtime.h>
#include <cstdint>

#define DB 64
#define DS 2048
#define DI 64
#define DH 128

typedef unsigned long long u64;

// ---------------- scratch (__device__ globals) -------------------------------
__device__ float g_wx0 [DB * DS * DH];   // x @ w0 (precomputed by gemm)
__device__ float g_out0[DB * DS * DH];   // layer-0 outputs
__device__ float g_wx1 [DB * DS * DH];   // out0 @ w1 (wx1 CTAs)
__device__ int   g_prog[DB * 32];        // [b*32]=p0  [+16]=pwx1

// ---------------- packed f32x2 helpers ---------------------------------------
__device__ __forceinline__ u64 ffma2(u64 a, u64 b, u64 c) {
    u64 d; asm("fma.rn.f32x2 %0, %1, %2, %3;" : "=l"(d) : "l"(a), "l"(b), "l"(c)); return d;
}
__device__ __forceinline__ u64 fadd2(u64 a, u64 b) {
    u64 d; asm("add.rn.f32x2 %0, %1, %2;" : "=l"(d) : "l"(a), "l"(b)); return d;
}
__device__ __forceinline__ u64 dup2(float x) {
    u64 d; asm("mov.b64 %0, {%1, %2};" : "=l"(d) : "f"(x), "f"(x)); return d;
}
__device__ __forceinline__ u64 pk2(float lo, float hi) {
    u64 d; asm("mov.b64 %0, {%1, %2};" : "=l"(d) : "f"(lo), "f"(hi)); return d;
}
__device__ __forceinline__ float2 unp2(u64 v) {
    float lo, hi; asm("mov.b64 {%0, %1}, %2;" : "=f"(lo), "=f"(hi) : "l"(v));
    return make_float2(lo, hi);
}

// ---------------- fast gates (verified, rel_err ~1.3e-7) ----------------------
__device__ __forceinline__ float sigm_fast(float x) {
    float t, r;
    asm("ex2.approx.f32 %0, %1;" : "=f"(t) : "f"(-1.4426950408889634f * x));
    asm("rcp.approx.f32 %0, %1;" : "=f"(r) : "f"(1.0f + t));
    return r;
}
__device__ __forceinline__ float tanh_fast(float x) {
    float t, r;
    asm("ex2.approx.f32 %0, %1;" : "=f"(t) : "f"(-2.8853900817779268f * x));
    asm("rcp.approx.f32 %0, %1;" : "=f"(r) : "f"(1.0f + t));
    return __fmaf_rn(2.0f, r, -1.0f);
}

// ---------------- flags --------------------------------------------------------
__device__ __forceinline__ int ld_acq(const int* p) {
    int v; asm volatile("ld.acquire.gpu.b32 %0, [%1];" : "=r"(v) : "l"(p)); return v;
}
__device__ __forceinline__ void st_rel(int* p, int v) {
    asm volatile("st.release.gpu.b32 [%0], %1;" :: "l"(p), "r"(v));
}
__device__ __forceinline__ void spin_ge(const int* p, int target) {
    while (ld_acq(p) < target) __nanosleep(32);
}

__global__ void reset_kernel() {
    int i = blockIdx.x * blockDim.x + threadIdx.x;
    if (i < DB * 32) g_prog[i] = 0;
}

// ============================================================================
// GEMM: OUT[row, 0:128] = X[row, 0:K] @ W[K,128]. One row per thread. (~70us)
// ============================================================================
template<int K>
__global__ void __launch_bounds__(256, 1) gemm_rows(
    const float* __restrict__ X, const float* __restrict__ W, float* __restrict__ OUT)
{
    extern __shared__ float ws[];
    for (int i = threadIdx.x; i < K * DH / 4; i += 256)
        reinterpret_cast<float4*>(ws)[i] = reinterpret_cast<const float4*>(W)[i];
    __syncthreads();

    int row = blockIdx.x * 256 + threadIdx.x;
    const float* xr = X + (size_t)row * K;
    float xv[K];
    #pragma unroll
    for (int i = 0; i < K / 4; i++) {
        float4 v = reinterpret_cast<const float4*>(xr)[i];
        xv[4*i] = v.x; xv[4*i+1] = v.y; xv[4*i+2] = v.z; xv[4*i+3] = v.w;
    }
    const u64* wsu = reinterpret_cast<const u64*>(ws);
    float* outr = OUT + (size_t)row * DH;

    #pragma unroll 1
    for (int cb = 0; cb < 16; cb++) {
        u64 a0 = 0, a1 = 0, a2 = 0, a3 = 0;
        #pragma unroll 16
        for (int k = 0; k < K; k++) {
            u64 xd = dup2(xv[k]);
            const u64* wr = wsu + k * (DH / 2) + cb * 4;
            a0 = ffma2(xd, wr[0], a0);
            a1 = ffma2(xd, wr[1], a1);
            a2 = ffma2(xd, wr[2], a2);
            a3 = ffma2(xd, wr[3], a3);
        }
        float2 r0 = unp2(a0), r1 = unp2(a1), r2 = unp2(a2), r3 = unp2(a3);
        reinterpret_cast<float4*>(outr)[cb*2]     = make_float4(r0.x, r0.y, r1.x, r1.y);
        reinterpret_cast<float4*>(outr)[cb*2 + 1] = make_float4(r2.x, r2.y, r3.x, r3.y);
    }
}

// ---------------- shared memory (20.5KB -> 2 CTAs/SM) --------------------------
struct ProjSM { float stage[8 * DH]; u64 part[8 * 4 * 64]; };   // 4KB + 16KB
struct ScanSM { float hbuf[2 * DH]; };
union PipeSM { ProjSM p; ScanSM s; };

// ============================================================================
// Scan role: 256 threads; thread = (col j = tid>>1, khalf = tid&1).
// pre[j] = wx[s][j] + sum_k h[k]*u[k][j]; halves combined via shfl.xor(1).
// One __syncthreads per step; depth-2 h ping-pong; wx depth-2 reg prefetch.
// pwait == nullptr -> completely wait-free (producer).
// ============================================================================
__device__ void scan_role(
    float* __restrict__ hbuf,
    const float* __restrict__ umat, const float* __restrict__ wx,
    const float* __restrict__ bg, const float* __restrict__ bu,
    const float* __restrict__ zeta, const float* __restrict__ nu,
    const float* __restrict__ lambd, const float* __restrict__ gamma,
    float* __restrict__ outp, float* __restrict__ hT,
    const int* pwait, int* ppost, int tid)
{
    const int j  = tid >> 1;
    const int kh = tid & 1;

    u64 uk[32];
    #pragma unroll
    for (int i = 0; i < 32; i++) {
        int k = kh * 64 + 2 * i;
        uk[i] = pk2(umat[(size_t)k * DH + j], umat[(size_t)(k + 1) * DH + j]);
    }
    const float bgj  = bg[j], buj = bu[j];
    const float sz   = sigm_fast(zeta[0]);
    const float sn   = sigm_fast(nu[0]);
    const float gc   = fminf(fmaxf(gamma[0], 0.f), 1.f);
    const float cadd = (1.f - gc) * lambd[0];

    hbuf[tid] = 0.f;                               // zero both ping-pong buffers
    if (pwait && tid == 0) spin_ge(pwait, 16);
    __syncthreads();

    float hold = 0.f, wxA = 0.f, wxB = 0.f;
    if (kh == 0) { wxA = wx[j]; wxB = wx[DH + j]; }

    #pragma unroll 1
    for (int s = 0; s < DS; s++) {
        if (pwait && (s & 7) == 0 && s) {
            if (tid == 0) {
                int t = s + 16; if (t > DS) t = DS;
                spin_ge(pwait, t);
            }
            __syncthreads();
        }
        const ulonglong2* hp =
            reinterpret_cast<const ulonglong2*>(hbuf + (s & 1) * DH + kh * 64);
        u64 a0 = 0, a1 = 0, a2 = 0, a3 = 0;
        #pragma unroll
        for (int t = 0; t < 8; t++) {
            ulonglong2 q0 = hp[2*t], q1 = hp[2*t + 1];
            a0 = ffma2(q0.x, uk[4*t + 0], a0);
            a1 = ffma2(q0.y, uk[4*t + 1], a1);
            a2 = ffma2(q1.x, uk[4*t + 2], a2);
            a3 = ffma2(q1.y, uk[4*t + 3], a3);
        }
        u64 acc = fadd2(fadd2(a0, a1), fadd2(a2, a3));
        acc = fadd2(acc, __shfl_xor_sync(0xFFFFFFFFu, acc, 1));
        float2 ap = unp2(acc);
        float pre = ap.x + ap.y;
        if (kh == 0) {
            pre += wxA;
            float zg = sigm_fast(pre + bgj);
            float th = tanh_fast(pre + buj);
            float hn = zg * hold + (sz * (1.f - zg) + sn) * th;
            float hc = __fmaf_rn(gc, hn, cadd);
            hold = hc;
            hbuf[((s & 1) ^ 1) * DH + j] = hc;
            outp[(size_t)s * DH + j] = hc;
            wxA = wxB;
            wxB = (s + 2 < DS) ? wx[(size_t)(s + 2) * DH + j] : 0.f;
        }
        __syncthreads();
        if (ppost && (s & 7) == 7 && tid == 0) {
            __threadfence();
            st_rel(ppost, s + 1);
        }
    }
    if (kh == 0) hT[j] = hold;
}

// ============================================================================
// wx1 role: dedicated chase CTA. wx1[t, :] = out0[t, :] @ w1, 8-row chunks.
// thread = (col pair c = tid&63, k-quarter q = tid>>6); weights in registers.
// ============================================================================
__device__ void wx1_role(
    const float* __restrict__ out0b, const float* __restrict__ w1,
    float* __restrict__ wx1b, const int* p0, int* pwx1,
    float* __restrict__ stage, u64* __restrict__ part, int tid)
{
    const int c = tid & 63;
    const int q = tid >> 6;

    u64 uw[32];
    #pragma unroll
    for (int i = 0; i < 32; i++)
        uw[i] = *reinterpret_cast<const u64*>(w1 + (size_t)(q * 32 + i) * DH + 2 * c);

    #pragma unroll 1
    for (int n = 0; n < DS / 8; n++) {
        const int t0 = n * 8;
        if (tid == 0) spin_ge(p0, t0 + 8);
        __syncthreads();

        // stage 8 rows of out0 (1024 floats, one float4 per thread)
        reinterpret_cast<float4*>(stage)[tid] =
            reinterpret_cast<const float4*>(out0b + (size_t)t0 * DH)[tid];
        __syncthreads();

        #pragma unroll 1
        for (int r = 0; r < 8; r++) {
            const float4* src = reinterpret_cast<const float4*>(stage + r * DH + q * 32);
            u64 acc0 = 0, acc1 = 0;
            #pragma unroll
            for (int i4 = 0; i4 < 8; i4++) {
                float4 v = src[i4];
                acc0 = ffma2(dup2(v.x), uw[4*i4 + 0], acc0);
                acc1 = ffma2(dup2(v.y), uw[4*i4 + 1], acc1);
                acc0 = ffma2(dup2(v.z), uw[4*i4 + 2], acc0);
                acc1 = ffma2(dup2(v.w), uw[4*i4 + 3], acc1);
            }
            part[(r * 4 + q) * 64 + c] = fadd2(acc0, acc1);
        }
        __syncthreads();

        #pragma unroll
        for (int o = tid; o < 512; o += 256) {
            int r = o >> 6, cc = o & 63;
            u64 s = fadd2(fadd2(part[(r*4 + 0)*64 + cc], part[(r*4 + 1)*64 + cc]),
                          fadd2(part[(r*4 + 2)*64 + cc], part[(r*4 + 3)*64 + cc]));
            *reinterpret_cast<u64*>(wx1b + (size_t)(t0 + r) * DH + 2 * cc) = s;
        }
        __threadfence();
        __syncthreads();
        if (tid == 0) st_rel(pwx1, t0 + 8);
    }
}

// ============================================================================
__global__ void __launch_bounds__(256, 2) pipe_kernel(
    const float* __restrict__ u0, const float* __restrict__ u1,
    const float* __restrict__ w1,
    const float* __restrict__ bg0, const float* __restrict__ bu0,
    const float* __restrict__ zeta0, const float* __restrict__ nu0,
    const float* __restrict__ lambd0, const float* __restrict__ gamma0,
    const float* __restrict__ bg1, const float* __restrict__ bu1,
    const float* __restrict__ zeta1, const float* __restrict__ nu1,
    const float* __restrict__ lambd1, const float* __restrict__ gamma1,
    float* __restrict__ out1, float* __restrict__ hT0, float* __restrict__ hT1)
{
    __shared__ __align__(16) PipeSM sm;

    const int tid  = threadIdx.x;
    const int role = blockIdx.x >> 6;   // 0=producer, 1=consumer, 2=wx1
    const int b    = blockIdx.x & 63;

    float*       out0b = g_out0 + (size_t)b * DS * DH;
    const float* wx0b  = g_wx0  + (size_t)b * DS * DH;
    float*       wx1b  = g_wx1  + (size_t)b * DS * DH;
    int*         p0    = g_prog + b * 32;
    int*         pwx1  = g_prog + b * 32 + 16;

    if (role == 0) {
        scan_role(sm.s.hbuf, u0, wx0b, bg0, bu0, zeta0, nu0, lambd0, gamma0,
                  out0b, hT0 + (size_t)b * DH, nullptr, p0, tid);
    } else if (role == 1) {
        scan_role(sm.s.hbuf, u1, wx1b, bg1, bu1, zeta1, nu1, lambd1, gamma1,
                  out1 + (size_t)b * DS * DH, hT1 + (size_t)b * DH,
                  pwx1, nullptr, tid);
    } else {
        wx1_role(out0b, w1, wx1b, p0, pwx1, sm.p.stage, sm.p.part, tid);
    }
}

// ============================================================================
extern "C" void kernel_launch(void* const* d_in, const int* in_sizes, int n_in,
                              void* d_out, int out_size)
{
    const float* x      = (const float*)d_in[0];
    const float* w0     = (const float*)d_in[1];
    const float* u0     = (const float*)d_in[2];
    const float* bg0    = (const float*)d_in[3];
    const float* bu0    = (const float*)d_in[4];
    const float* zeta0  = (const float*)d_in[5];
    const float* nu0    = (const float*)d_in[6];
    const float* lambd0 = (const float*)d_in[7];
    const float* gamma0 = (const float*)d_in[8];
    const float* w1     = (const float*)d_in[9];
    const float* u1     = (const float*)d_in[10];
    const float* bg1    = (const float*)d_in[11];
    const float* bu1    = (const float*)d_in[12];
    const float* zeta1  = (const float*)d_in[13];
    const float* nu1    = (const float*)d_in[14];
    const float* lambd1 = (const float*)d_in[15];
    const float* gamma1 = (const float*)d_in[16];
    (void)in_sizes; (void)n_in; (void)out_size;

    float* out = (float*)d_out;                    // out1: [B, S, H]
    float* hT0 = out + (size_t)DB * DS * DH;       // h_n[0]
    float* hT1 = hT0 + (size_t)DB * DH;            // h_n[1]

    void* p;
    cudaGetSymbolAddress(&p, g_wx0);
    float* wx0p = (float*)p;

    static int smem_set = 0;
    if (!smem_set) {
        cudaFuncSetAttribute(gemm_rows<DI>,
                             cudaFuncAttributeMaxDynamicSharedMemorySize, DI * DH * 4);
        smem_set = 1;
    }

    reset_kernel<<<2, 1024>>>();
    gemm_rows<DI><<<(DB * DS) / 256, 256, DI * DH * 4>>>(x, w0, wx0p);
    pipe_kernel<<<3 * DB, 256>>>(
        u0, u1, w1,
        bg0, bu0, zeta0, nu0, lambd0, gamma0,
        bg1, bu1, zeta1, nu1, lambd1, gamma1,
        out, hT0, hT1);
}